// round 10
// baseline (speedup 1.0000x reference)
#include <cuda_runtime.h>

#define N_QUBITS 10
#define TPB 64
#define SPT 2   // samples per thread: 20 floats = 5 aligned float4 (byte 80*p)

// Closed-form evaluation of the 10-qubit staircase circuit:
//   E_0 = cos(x_0 + r_0)
//   E_i = cos(x_i + r_i) * ((1-k_{i-1}) + k_{i-1} * E_{i-1}),  k_j = (1 - cos e_j)/2
// (R0 derivation: each entangling gate is diagonal in its control qubit's Z
// basis, so <Z_i> is fixed after gate (i-1,i); only the diagonal of the 2x2
// reduced density matrix propagates -> 10-step scalar recurrence per sample.)
//
// Two samples per thread amortizes the parameter fetch + k = sin^2(e/2)
// MUFU work (the dominant per-thread cost after R9 showed the timed loop is
// issue-count bound) and upgrades data traffic to LDG.128/STG.128.
// 8192 threads = 128 CTAs x 64 — keeps the 128-CTA single-wave shape.
__global__ void __launch_bounds__(TPB, 1)
qsa_closed_form_kernel(const float4* __restrict__ inputs4,
                       const float* __restrict__ rot,
                       const float* __restrict__ ent,
                       float4* __restrict__ out4) {
    const int p = blockIdx.x * TPB + threadIdx.x;   // sample-pair index, exact fit

    // 5 independent LDG.128 (MLP = 5): 20 floats = 2 samples.
    float4 v[5];
    const float4* src = inputs4 + p * 5;
    #pragma unroll
    for (int i = 0; i < 5; i++) v[i] = src[i];

    // Vectorized uniform broadcast loads of the parameter vectors.
    float r[N_QUBITS];
    {
        float4 r0 = __ldg(reinterpret_cast<const float4*>(rot));      // rot[0..3]
        float4 r1 = __ldg(reinterpret_cast<const float4*>(rot) + 1);  // rot[4..7]
        float2 r2 = __ldg(reinterpret_cast<const float2*>(rot) + 4);  // rot[8..9]
        r[0] = r0.x; r[1] = r0.y; r[2] = r0.z; r[3] = r0.w;
        r[4] = r1.x; r[5] = r1.y; r[6] = r1.z; r[7] = r1.w;
        r[8] = r2.x; r[9] = r2.y;
    }
    float ev_raw[N_QUBITS - 1];
    {
        float4 e0 = __ldg(reinterpret_cast<const float4*>(ent));      // ent[0..3]
        float4 e1 = __ldg(reinterpret_cast<const float4*>(ent) + 1);  // ent[4..7]
        float  e2 = __ldg(ent + 8);                                   // ent[8]
        ev_raw[0] = e0.x; ev_raw[1] = e0.y; ev_raw[2] = e0.z; ev_raw[3] = e0.w;
        ev_raw[4] = e1.x; ev_raw[5] = e1.y; ev_raw[6] = e1.z; ev_raw[7] = e1.w;
        ev_raw[8] = e2;
    }
    float k[N_QUBITS - 1], kc[N_QUBITS - 1];
    #pragma unroll
    for (int i = 0; i < N_QUBITS - 1; i++) {
        float kk = 0.5f - 0.5f * __cosf(ev_raw[i]);   // sin^2(e/2), shared by both samples
        k[i]  = kk;
        kc[i] = 1.0f - kk;
    }

    float x[20];
    #pragma unroll
    for (int i = 0; i < 5; i++) {
        x[4*i+0] = v[i].x; x[4*i+1] = v[i].y; x[4*i+2] = v[i].z; x[4*i+3] = v[i].w;
    }

    // 20 independent cos (pipelined MUFU); two independent 2-op carry chains.
    float c[20];
    #pragma unroll
    for (int s = 0; s < SPT; s++)
        #pragma unroll
        for (int i = 0; i < N_QUBITS; i++)
            c[s * N_QUBITS + i] = __cosf(x[s * N_QUBITS + i] + r[i]);

    float e[20];
    #pragma unroll
    for (int s = 0; s < SPT; s++) {
        float carry = 1.0f;
        #pragma unroll
        for (int i = 0; i < N_QUBITS; i++) {
            float ev = c[s * N_QUBITS + i] * carry;
            e[s * N_QUBITS + i] = ev;
            if (i < N_QUBITS - 1) carry = __fmaf_rn(k[i], ev, kc[i]);
        }
    }

    // 5 STG.128.
    float4* dst = out4 + p * 5;
    #pragma unroll
    for (int i = 0; i < 5; i++) {
        float4 o;
        o.x = e[4*i+0]; o.y = e[4*i+1]; o.z = e[4*i+2]; o.w = e[4*i+3];
        dst[i] = o;
    }
}

extern "C" void kernel_launch(void* const* d_in, const int* in_sizes, int n_in,
                              void* d_out, int out_size) {
    const float* inputs = (const float*)d_in[0];  // (16, 1024, 10) fp32
    const float* rot    = (const float*)d_in[1];  // (10,)
    const float* ent    = (const float*)d_in[2];  // (9,)
    float* out = (float*)d_out;

    int total_elems = in_sizes[0];                 // 163840
    int T = total_elems / N_QUBITS;                // 16384 samples
    int n_pairs = T / SPT;                         // 8192
    int blocks = n_pairs / TPB;                    // 128, exact

    qsa_closed_form_kernel<<<blocks, TPB>>>(
        reinterpret_cast<const float4*>(inputs), rot, ent,
        reinterpret_cast<float4*>(out));
}